// round 11
// baseline (speedup 1.0000x reference)
#include <cuda_runtime.h>
#include <cuda_fp16.h>
#include <mma.h>
#include <cstdint>
#include <cstddef>

using namespace nvcuda;

// ---------------------------------------------------------------------------
// Problem constants
// ---------------------------------------------------------------------------
constexpr int NTOK = 2048;          // B*S
constexpr int DDIM = 256;
constexpr int VTOT = 50000;
constexpr int VMAX = 20000;

// GEMM tiling (R8 config): BM=128 BN=128 BK=64, 3-stage cp.async pipeline
constexpr int BM = 128, BN = 128, BK = 64;
constexpr int LDS = BK + 8;                         // 72 halves = 144 B row stride
constexpr int LDC = BN + 8;                         // epilogue fp32 stride
constexpr int A_BYTES = BM * LDS * 2;               // 18432
constexpr int B_BYTES = BN * LDS * 2;               // 18432
constexpr int STAGE_BYTES = A_BYTES + B_BYTES;      // 36864
constexpr int PIPE = 3;
constexpr int GEMM_SMEM = PIPE * STAGE_BYTES;       // 110592
constexpr int GEMM_THREADS = 256;
constexpr int NCHUNK = DDIM / BK;                   // 4
constexpr int GEMM_BLOCKS = 592;                    // ~2 CTAs/SM, one resident wave

constexpr int OUT_THREADS = 512;
constexpr int RMAX = 10;                            // ceil((20000/4)/512)

constexpr int NB0 = (20000 + BN - 1) / BN;          // 157
constexpr int NB2 = (10000 + BN - 1) / BN;          // 79
constexpr int MAXTILES = 16 * NB0 * 2 + 16 * NB2;   // worst case 6288

// element counts for the fp16 conversion
constexpr size_t XN  = (size_t)NTOK * DDIM;
constexpr size_t W0N = (size_t)20000 * DDIM;
constexpr size_t W1N = (size_t)20000 * DDIM;
constexpr size_t W2N = (size_t)10000 * DDIM;
constexpr size_t TOTN = XN + W0N + W1N + W2N;       // 13324288 (divisible by 8)

// ---------------------------------------------------------------------------
// Device scratch
// ---------------------------------------------------------------------------
__device__ int    g_cnt[3];
__device__ int    g_tok[3][NTOK];
__device__ int    g_clu[NTOK];
__device__ int    g_ntile;
__device__ int    g_tmap[MAXTILES];                 // packed c<<16 | mb<<8 | nb
__device__ __half g_xh[XN];
__device__ __half g_wh[W0N + W1N + W2N];
__device__ __half g_scratch[(size_t)NTOK * VMAX];   // fp16 logits, stride VMAX

// ---------------------------------------------------------------------------
// Helpers
// ---------------------------------------------------------------------------
__device__ __forceinline__ void cp_async16(uint32_t dst, const void* src, bool pred) {
    int sz = pred ? 16 : 0;
    asm volatile("cp.async.cg.shared.global [%0], [%1], 16, %2;"
                 :: "r"(dst), "l"(src), "r"(sz));
}
__device__ __forceinline__ void cp_commit() { asm volatile("cp.async.commit_group;"); }
template <int N>
__device__ __forceinline__ void cp_wait() { asm volatile("cp.async.wait_group %0;" :: "n"(N)); }
__device__ __forceinline__ uint32_t smem_u32(const void* p) {
    uint32_t a;
    asm("{ .reg .u64 t; cvta.to.shared.u64 t, %1; cvt.u32.u64 %0, t; }" : "=r"(a) : "l"(p));
    return a;
}

// ---------------------------------------------------------------------------
// Kernel 1: fp32 -> fp16 conversion (8 elems/thread); block 0 builds the
// token lists AND the compact GEMM tile map.
// ---------------------------------------------------------------------------
__global__ void prep_kernel(const float* __restrict__ x,
                            const float* __restrict__ w0, const float* __restrict__ w1,
                            const float* __restrict__ w2, const int* __restrict__ tg)
{
    size_t i = (size_t)blockIdx.x * blockDim.x + threadIdx.x;
    size_t j = i * 8;
    if (j < TOTN) {
        const float* src; __half* dst;
        if (j < XN) { src = x + j; dst = g_xh + j; }
        else {
            size_t k = j - XN;
            if (k < W0N)            { src = w0 + k;               dst = g_wh + k; }
            else if (k < W0N + W1N) { src = w1 + (k - W0N);       dst = g_wh + k; }
            else                    { src = w2 + (k - W0N - W1N); dst = g_wh + k; }
        }
        float4 v0 = *(const float4*)src;
        float4 v1 = *(const float4*)(src + 4);
        __half2 h[4] = { __floats2half2_rn(v0.x, v0.y), __floats2half2_rn(v0.z, v0.w),
                         __floats2half2_rn(v1.x, v1.y), __floats2half2_rn(v1.z, v1.w) };
        *(uint4*)dst = *(const uint4*)h;
    }

    if (blockIdx.x == 0) {
        __shared__ int s_cnt[3];
        __shared__ int s_is64;
        if (threadIdx.x == 0) s_is64 = 1;
        if (threadIdx.x < 3) s_cnt[threadIdx.x] = 0;
        __syncthreads();
        for (int q = threadIdx.x; q < NTOK / 2; q += blockDim.x)
            if (tg[2 * q + 1] != 0) s_is64 = 0;
        __syncthreads();
        int is64 = s_is64;
        for (int t = threadIdx.x; t < NTOK; t += blockDim.x) {
            int v = is64 ? tg[2 * t] : tg[t];
            int c = (v < 20000) ? 0 : ((v < 40000) ? 1 : 2);
            g_clu[t] = c;
            int pos = atomicAdd(&s_cnt[c], 1);
            g_tok[c][pos] = t;
        }
        __syncthreads();
        if (threadIdx.x < 3) g_cnt[threadIdx.x] = s_cnt[threadIdx.x];

        // Build compact tile map: per cluster, mb-fastest within nb so that
        // consecutive tiles (handled by concurrent blocks) share the B tile.
        int mb0 = (s_cnt[0] + BM - 1) / BM;
        int mb1 = (s_cnt[1] + BM - 1) / BM;
        int mb2 = (s_cnt[2] + BM - 1) / BM;
        int tot0 = mb0 * NB0, tot1 = mb1 * NB0, tot2 = mb2 * NB2;
        int total = tot0 + tot1 + tot2;
        if (threadIdx.x == 0) g_ntile = total;
        for (int q = threadIdx.x; q < total; q += blockDim.x) {
            int c, rel, mbc;
            if (q < tot0)             { c = 0; rel = q;               mbc = mb0; }
            else if (q < tot0 + tot1) { c = 1; rel = q - tot0;        mbc = mb1; }
            else                      { c = 2; rel = q - tot0 - tot1; mbc = mb2; }
            int nb = rel / mbc;
            int mb = rel - nb * mbc;
            g_tmap[q] = (c << 16) | (mb << 8) | nb;
        }
    }
}

// ---------------------------------------------------------------------------
// Kernel 2: persistent grouped fp16 GEMM over the live-tile worklist
// ---------------------------------------------------------------------------
__global__ __launch_bounds__(GEMM_THREADS, 2) void gemm_kernel(
    const float* __restrict__ b0, const float* __restrict__ b1, const float* __restrict__ b2)
{
    extern __shared__ char smem[];
    const uint32_t sb = smem_u32(smem);
    const int tid  = threadIdx.x;
    const int warp = tid >> 5;
    const int wm = warp >> 1;       // 0..3 : 32-row slab
    const int wn = warp & 1;        // 0..1 : 64-col slab
    const int ntile = g_ntile;

    for (int tix = blockIdx.x; tix < ntile; tix += GEMM_BLOCKS) {
        const int packed = g_tmap[tix];
        const int c  = packed >> 16;
        const int mb = (packed >> 8) & 0xFF;
        const int nb = packed & 0xFF;
        const int cnt = g_cnt[c];
        const int m_base = mb * BM;
        const int Vc = (c == 2) ? 10000 : 20000;
        const int n_base = nb * BN;

        const size_t woff = (c == 0) ? 0 : ((c == 1) ? W0N : (W0N + W1N));
        const float* __restrict__ bias = (c == 0) ? b0 : ((c == 1) ? b1 : b2);

        const __half* arow[4];
        #pragma unroll
        for (int j = 0; j < 4; j++) {
            int row = (tid + GEMM_THREADS * j) >> 3;
            int m = m_base + row;
            arow[j] = (m < cnt) ? (g_xh + (size_t)g_tok[c][m] * DDIM) : nullptr;
        }
        const __half* brow[4];
        bool bval[4];
        #pragma unroll
        for (int j = 0; j < 4; j++) {
            int row = (tid + GEMM_THREADS * j) >> 3;
            int n = n_base + row;
            bval[j] = (n < Vc);
            brow[j] = g_wh + (woff + (size_t)(bval[j] ? n : 0) * DDIM);
        }

        auto stage_load = [&](int s) {
            const uint32_t abase = sb + (s % PIPE) * STAGE_BYTES;
            const uint32_t bbase = abase + A_BYTES;
            #pragma unroll
            for (int j = 0; j < 4; j++) {
                int idx = tid + GEMM_THREADS * j;
                int row = idx >> 3, seg = idx & 7;
                const __half* src = arow[j] ? (arow[j] + s * BK + seg * 8) : g_xh;
                cp_async16(abase + row * (LDS * 2) + seg * 16, src, arow[j] != nullptr);
            }
            #pragma unroll
            for (int j = 0; j < 4; j++) {
                int idx = tid + GEMM_THREADS * j;
                int row = idx >> 3, seg = idx & 7;
                cp_async16(bbase + row * (LDS * 2) + seg * 16, brow[j] + s * BK + seg * 8, bval[j]);
            }
            cp_commit();
        };

        wmma::fragment<wmma::accumulator, 16, 16, 16, float> acc[2][4];
        #pragma unroll
        for (int i = 0; i < 2; i++)
            #pragma unroll
            for (int j = 0; j < 4; j++)
                wmma::fill_fragment(acc[i][j], 0.0f);

        stage_load(0); stage_load(1);

        #pragma unroll
        for (int k = 0; k < NCHUNK; k++) {
            if (k < NCHUNK - 1) cp_wait<1>(); else cp_wait<0>();
            __syncthreads();
            if (k + 2 < NCHUNK) stage_load(k + 2);
            const __half* As = (const __half*)(smem + (k % PIPE) * STAGE_BYTES);
            const __half* Bs = As + A_BYTES / 2;
            #pragma unroll
            for (int kk = 0; kk < BK; kk += 16) {
                wmma::fragment<wmma::matrix_a, 16, 16, 16, __half, wmma::row_major> af[2];
                wmma::fragment<wmma::matrix_b, 16, 16, 16, __half, wmma::col_major> bf[4];
                #pragma unroll
                for (int i = 0; i < 2; i++)
                    wmma::load_matrix_sync(af[i], As + (wm * 32 + i * 16) * LDS + kk, LDS);
                #pragma unroll
                for (int j = 0; j < 4; j++)
                    wmma::load_matrix_sync(bf[j], Bs + (wn * 64 + j * 16) * LDS + kk, LDS);
                #pragma unroll
                for (int i = 0; i < 2; i++)
                    #pragma unroll
                    for (int j = 0; j < 4; j++)
                        wmma::mma_sync(acc[i][j], af[i], bf[j], acc[i][j]);
            }
        }
        __syncthreads();

        float* Cs = (float*)smem;   // [BM][LDC] = 69632 B <= GEMM_SMEM
        #pragma unroll
        for (int i = 0; i < 2; i++)
            #pragma unroll
            for (int j = 0; j < 4; j++)
                wmma::store_matrix_sync(Cs + (wm * 32 + i * 16) * LDC + wn * 64 + j * 16,
                                        acc[i][j], LDC, wmma::mem_row_major);
        __syncthreads();

        for (int idx = tid; idx < BM * (BN / 8); idx += GEMM_THREADS) {
            int row = idx >> 4, q = idx & 15;
            int m = m_base + row;
            if (m >= cnt) continue;
            int n = n_base + q * 8;
            if (n >= Vc) continue;
            __half* srow = g_scratch + (size_t)g_tok[c][m] * VMAX;
            const float* src = Cs + row * LDC + q * 8;
            float4 bv0 = *(const float4*)(bias + n);
            float4 bv1 = *(const float4*)(bias + n + 4);
            __half2 h[4] = { __floats2half2_rn(src[0] + bv0.x, src[1] + bv0.y),
                             __floats2half2_rn(src[2] + bv0.z, src[3] + bv0.w),
                             __floats2half2_rn(src[4] + bv1.x, src[5] + bv1.y),
                             __floats2half2_rn(src[6] + bv1.z, src[7] + bv1.w) };
            *(uint4*)(srow + n) = *(const uint4*)h;
        }
        __syncthreads();   // Cs / stage buffers reused by next tile
    }
}

// ---------------------------------------------------------------------------
// Kernel 3: fused lse + full-row output, register-resident logits.
// ---------------------------------------------------------------------------
__global__ __launch_bounds__(OUT_THREADS, 2) void out_kernel(float* __restrict__ out) {
    __shared__ float red[16];
    __shared__ float sh_bcast;

    const int t = blockIdx.x;
    const int c = g_clu[t];
    const int l = c * 20000;
    const int V = (c == 2) ? 10000 : 20000;
    const int nf4 = V >> 2;                         // 5000 or 2500
    const __half* __restrict__ rowp = g_scratch + (size_t)t * VMAX;
    const int tid = threadIdx.x;

    float4 r[RMAX];
    float lmax = -3.4e38f;
    #pragma unroll
    for (int it = 0; it < RMAX; it++) {
        int j = tid + it * OUT_THREADS;
        if (j < nf4) {
            uint2 u = *(const uint2*)(rowp + j * 4);
            float2 f0 = __half22float2(*(const __half2*)&u.x);
            float2 f1 = __half22float2(*(const __half2*)&u.y);
            r[it] = make_float4(f0.x, f0.y, f1.x, f1.y);
            lmax = fmaxf(lmax, fmaxf(fmaxf(r[it].x, r[it].y), fmaxf(r[it].z, r[it].w)));
        }
    }
    #pragma unroll
    for (int o = 16; o; o >>= 1) lmax = fmaxf(lmax, __shfl_xor_sync(0xffffffffu, lmax, o));
    if ((tid & 31) == 0) red[tid >> 5] = lmax;
    __syncthreads();
    if (tid < 32) {
        float v = (tid < 16) ? red[tid] : -3.4e38f;
        #pragma unroll
        for (int o = 8; o; o >>= 1) v = fmaxf(v, __shfl_xor_sync(0xffffffffu, v, o));
        if (tid == 0) sh_bcast = fmaxf(v, 0.0f);    // implicit zeros join the max
    }
    __syncthreads();
    const float M = sh_bcast;

    float lsum = 0.f;
    #pragma unroll
    for (int it = 0; it < RMAX; it++) {
        int j = tid + it * OUT_THREADS;
        if (j < nf4)
            lsum += __expf(r[it].x - M) + __expf(r[it].y - M)
                  + __expf(r[it].z - M) + __expf(r[it].w - M);
    }
    #pragma unroll
    for (int o = 16; o; o >>= 1) lsum += __shfl_xor_sync(0xffffffffu, lsum, o);
    __syncthreads();
    if ((tid & 31) == 0) red[tid >> 5] = lsum;
    __syncthreads();
    if (tid < 32) {
        float v = (tid < 16) ? red[tid] : 0.f;
        #pragma unroll
        for (int o = 8; o; o >>= 1) v += __shfl_xor_sync(0xffffffffu, v, o);
        if (tid == 0)
            sh_bcast = M + logf(v + (float)(VTOT - V) * __expf(-M));   // implicit zeros
    }
    __syncthreads();
    const float lse = sh_bcast;
    const float neg = -lse;

    float4* o4 = (float4*)(out + (size_t)t * VTOT);
    const int l4 = l >> 2;
    #pragma unroll
    for (int it = 0; it < RMAX; it++) {
        int j = tid + it * OUT_THREADS;
        if (j < nf4)
            __stcs(&o4[l4 + j], make_float4(r[it].x - lse, r[it].y - lse,
                                            r[it].z - lse, r[it].w - lse));
    }
    const float4 nv = make_float4(neg, neg, neg, neg);
    for (int j = tid; j < l4; j += OUT_THREADS) __stcs(&o4[j], nv);
    for (int j = l4 + nf4 + tid; j < VTOT / 4; j += OUT_THREADS) __stcs(&o4[j], nv);
}

// ---------------------------------------------------------------------------
// Launch (single stream)
// ---------------------------------------------------------------------------
extern "C" void kernel_launch(void* const* d_in, const int* in_sizes, int n_in,
                              void* d_out, int out_size) {
    const float* x  = (const float*)d_in[0];
    const int*   tg = (const int*)d_in[1];
    const float* w0 = (const float*)d_in[2];
    const float* w1 = (const float*)d_in[3];
    const float* w2 = (const float*)d_in[4];
    const float* b0 = (const float*)d_in[5];
    const float* b1 = (const float*)d_in[6];
    const float* b2 = (const float*)d_in[7];
    float* out = (float*)d_out;

    cudaFuncSetAttribute(gemm_kernel, cudaFuncAttributeMaxDynamicSharedMemorySize, GEMM_SMEM);

    int prep_blocks = (int)((TOTN / 8 + 255) / 256);
    prep_kernel<<<prep_blocks, 256>>>(x, w0, w1, w2, tg);

    gemm_kernel<<<GEMM_BLOCKS, GEMM_THREADS, GEMM_SMEM>>>(b0, b1, b2);

    out_kernel<<<NTOK, OUT_THREADS>>>(out);
}

// round 12
// speedup vs baseline: 1.0261x; 1.0261x over previous
#include <cuda_runtime.h>
#include <cuda_fp16.h>
#include <mma.h>
#include <cstdint>
#include <cstddef>

using namespace nvcuda;

// ---------------------------------------------------------------------------
// Problem constants
// ---------------------------------------------------------------------------
constexpr int NTOK = 2048;          // B*S
constexpr int DDIM = 256;
constexpr int VTOT = 50000;
constexpr int VMAX = 20000;

// GEMM tiling (R8/R10 config): BM=128 BN=128 BK=64, 3-stage cp.async pipeline
constexpr int BM = 128, BN = 128, BK = 64;
constexpr int LDS = BK + 8;                         // 72 halves = 144 B row stride
constexpr int LDC = BN + 8;                         // epilogue fp32 stride
constexpr int A_BYTES = BM * LDS * 2;               // 18432
constexpr int B_BYTES = BN * LDS * 2;               // 18432
constexpr int STAGE_BYTES = A_BYTES + B_BYTES;      // 36864
constexpr int PIPE = 3;
constexpr int GEMM_SMEM = PIPE * STAGE_BYTES;       // 110592
constexpr int GEMM_THREADS = 256;
constexpr int NCHUNK = DDIM / BK;                   // 4
constexpr int GEMM_BLOCKS = 592;                    // 2 CTAs/SM, one resident wave

constexpr int OUT_THREADS = 512;
constexpr int RMAX = 10;                            // ceil((20000/4)/512)

constexpr int NB0 = (20000 + BN - 1) / BN;          // 157
constexpr int NB2 = (10000 + BN - 1) / BN;          // 79
constexpr int MAXTILES = 16 * NB0 * 2 + 16 * NB2;   // worst case 6288

// element counts for the fp16 conversion
constexpr size_t XN  = (size_t)NTOK * DDIM;
constexpr size_t W0N = (size_t)20000 * DDIM;
constexpr size_t W1N = (size_t)20000 * DDIM;
constexpr size_t W2N = (size_t)10000 * DDIM;
constexpr size_t TOTN = XN + W0N + W1N + W2N;       // 13324288 (divisible by 8)

// ---------------------------------------------------------------------------
// Device scratch
// ---------------------------------------------------------------------------
__device__ int    g_cnt[3];
__device__ int    g_tok[3][NTOK];
__device__ int    g_clu[NTOK];
__device__ int    g_ntile;
__device__ int    g_next;                           // dynamic tile ticket
__device__ int    g_tmap[MAXTILES];                 // packed c<<16 | mb<<8 | nb
__device__ __half g_xh[XN];
__device__ __half g_wh[W0N + W1N + W2N];
__device__ __half g_scratch[(size_t)NTOK * VMAX];   // fp16 logits, stride VMAX

// ---------------------------------------------------------------------------
// Helpers
// ---------------------------------------------------------------------------
__device__ __forceinline__ void cp_async16(uint32_t dst, const void* src, bool pred) {
    int sz = pred ? 16 : 0;
    asm volatile("cp.async.cg.shared.global [%0], [%1], 16, %2;"
                 :: "r"(dst), "l"(src), "r"(sz));
}
__device__ __forceinline__ void cp_commit() { asm volatile("cp.async.commit_group;"); }
template <int N>
__device__ __forceinline__ void cp_wait() { asm volatile("cp.async.wait_group %0;" :: "n"(N)); }
__device__ __forceinline__ uint32_t smem_u32(const void* p) {
    uint32_t a;
    asm("{ .reg .u64 t; cvta.to.shared.u64 t, %1; cvt.u32.u64 %0, t; }" : "=r"(a) : "l"(p));
    return a;
}

// ---------------------------------------------------------------------------
// Kernel 1: fp32 -> fp16 conversion (8 elems/thread); block 0 builds the
// token lists, the compact GEMM tile map, and resets the ticket counter.
// ---------------------------------------------------------------------------
__global__ void prep_kernel(const float* __restrict__ x,
                            const float* __restrict__ w0, const float* __restrict__ w1,
                            const float* __restrict__ w2, const int* __restrict__ tg)
{
    size_t i = (size_t)blockIdx.x * blockDim.x + threadIdx.x;
    size_t j = i * 8;
    if (j < TOTN) {
        const float* src; __half* dst;
        if (j < XN) { src = x + j; dst = g_xh + j; }
        else {
            size_t k = j - XN;
            if (k < W0N)            { src = w0 + k;               dst = g_wh + k; }
            else if (k < W0N + W1N) { src = w1 + (k - W0N);       dst = g_wh + k; }
            else                    { src = w2 + (k - W0N - W1N); dst = g_wh + k; }
        }
        float4 v0 = *(const float4*)src;
        float4 v1 = *(const float4*)(src + 4);
        __half2 h[4] = { __floats2half2_rn(v0.x, v0.y), __floats2half2_rn(v0.z, v0.w),
                         __floats2half2_rn(v1.x, v1.y), __floats2half2_rn(v1.z, v1.w) };
        *(uint4*)dst = *(const uint4*)h;
    }

    if (blockIdx.x == 0) {
        __shared__ int s_cnt[3];
        __shared__ int s_is64;
        if (threadIdx.x == 0) { s_is64 = 1; g_next = 0; }
        if (threadIdx.x < 3) s_cnt[threadIdx.x] = 0;
        __syncthreads();
        for (int q = threadIdx.x; q < NTOK / 2; q += blockDim.x)
            if (tg[2 * q + 1] != 0) s_is64 = 0;
        __syncthreads();
        int is64 = s_is64;
        for (int t = threadIdx.x; t < NTOK; t += blockDim.x) {
            int v = is64 ? tg[2 * t] : tg[t];
            int c = (v < 20000) ? 0 : ((v < 40000) ? 1 : 2);
            g_clu[t] = c;
            int pos = atomicAdd(&s_cnt[c], 1);
            g_tok[c][pos] = t;
        }
        __syncthreads();
        if (threadIdx.x < 3) g_cnt[threadIdx.x] = s_cnt[threadIdx.x];

        // Compact tile map: mb-fastest within nb (consecutive tickets share B)
        int mb0 = (s_cnt[0] + BM - 1) / BM;
        int mb1 = (s_cnt[1] + BM - 1) / BM;
        int mb2 = (s_cnt[2] + BM - 1) / BM;
        int tot0 = mb0 * NB0, tot1 = mb1 * NB0, tot2 = mb2 * NB2;
        int total = tot0 + tot1 + tot2;
        if (threadIdx.x == 0) g_ntile = total;
        for (int q = threadIdx.x; q < total; q += blockDim.x) {
            int c, rel, mbc;
            if (q < tot0)             { c = 0; rel = q;               mbc = mb0; }
            else if (q < tot0 + tot1) { c = 1; rel = q - tot0;        mbc = mb1; }
            else                      { c = 2; rel = q - tot0 - tot1; mbc = mb2; }
            int nb = rel / mbc;
            int mb = rel - nb * mbc;
            g_tmap[q] = (c << 16) | (mb << 8) | nb;
        }
    }
}

// ---------------------------------------------------------------------------
// Kernel 2: persistent grouped fp16 GEMM, dynamic atomic-ticket scheduling
// ---------------------------------------------------------------------------
__global__ __launch_bounds__(GEMM_THREADS, 2) void gemm_kernel(
    const float* __restrict__ b0, const float* __restrict__ b1, const float* __restrict__ b2)
{
    extern __shared__ char smem[];
    __shared__ int s_tix;
    const uint32_t sb = smem_u32(smem);
    const int tid  = threadIdx.x;
    const int warp = tid >> 5;
    const int wm = warp >> 1;       // 0..3 : 32-row slab
    const int wn = warp & 1;        // 0..1 : 64-col slab
    const int ntile = g_ntile;

    for (;;) {
        if (tid == 0) s_tix = atomicAdd(&g_next, 1);
        __syncthreads();
        const int tix = s_tix;
        if (tix >= ntile) break;

        const int packed = g_tmap[tix];
        const int c  = packed >> 16;
        const int mb = (packed >> 8) & 0xFF;
        const int nb = packed & 0xFF;
        const int cnt = g_cnt[c];
        const int m_base = mb * BM;
        const int Vc = (c == 2) ? 10000 : 20000;
        const int n_base = nb * BN;

        const size_t woff = (c == 0) ? 0 : ((c == 1) ? W0N : (W0N + W1N));
        const float* __restrict__ bias = (c == 0) ? b0 : ((c == 1) ? b1 : b2);

        const __half* arow[4];
        #pragma unroll
        for (int j = 0; j < 4; j++) {
            int row = (tid + GEMM_THREADS * j) >> 3;
            int m = m_base + row;
            arow[j] = (m < cnt) ? (g_xh + (size_t)g_tok[c][m] * DDIM) : nullptr;
        }
        const __half* brow[4];
        bool bval[4];
        #pragma unroll
        for (int j = 0; j < 4; j++) {
            int row = (tid + GEMM_THREADS * j) >> 3;
            int n = n_base + row;
            bval[j] = (n < Vc);
            brow[j] = g_wh + (woff + (size_t)(bval[j] ? n : 0) * DDIM);
        }

        auto stage_load = [&](int s) {
            const uint32_t abase = sb + (s % PIPE) * STAGE_BYTES;
            const uint32_t bbase = abase + A_BYTES;
            #pragma unroll
            for (int j = 0; j < 4; j++) {
                int idx = tid + GEMM_THREADS * j;
                int row = idx >> 3, seg = idx & 7;
                const __half* src = arow[j] ? (arow[j] + s * BK + seg * 8) : g_xh;
                cp_async16(abase + row * (LDS * 2) + seg * 16, src, arow[j] != nullptr);
            }
            #pragma unroll
            for (int j = 0; j < 4; j++) {
                int idx = tid + GEMM_THREADS * j;
                int row = idx >> 3, seg = idx & 7;
                cp_async16(bbase + row * (LDS * 2) + seg * 16, brow[j] + s * BK + seg * 8, bval[j]);
            }
            cp_commit();
        };

        wmma::fragment<wmma::accumulator, 16, 16, 16, float> acc[2][4];
        #pragma unroll
        for (int i = 0; i < 2; i++)
            #pragma unroll
            for (int j = 0; j < 4; j++)
                wmma::fill_fragment(acc[i][j], 0.0f);

        stage_load(0); stage_load(1);

        #pragma unroll
        for (int k = 0; k < NCHUNK; k++) {
            if (k < NCHUNK - 1) cp_wait<1>(); else cp_wait<0>();
            __syncthreads();
            if (k + 2 < NCHUNK) stage_load(k + 2);
            const __half* As = (const __half*)(smem + (k % PIPE) * STAGE_BYTES);
            const __half* Bs = As + A_BYTES / 2;
            #pragma unroll
            for (int kk = 0; kk < BK; kk += 16) {
                wmma::fragment<wmma::matrix_a, 16, 16, 16, __half, wmma::row_major> af[2];
                wmma::fragment<wmma::matrix_b, 16, 16, 16, __half, wmma::col_major> bf[4];
                #pragma unroll
                for (int i = 0; i < 2; i++)
                    wmma::load_matrix_sync(af[i], As + (wm * 32 + i * 16) * LDS + kk, LDS);
                #pragma unroll
                for (int j = 0; j < 4; j++)
                    wmma::load_matrix_sync(bf[j], Bs + (wn * 64 + j * 16) * LDS + kk, LDS);
                #pragma unroll
                for (int i = 0; i < 2; i++)
                    #pragma unroll
                    for (int j = 0; j < 4; j++)
                        wmma::mma_sync(acc[i][j], af[i], bf[j], acc[i][j]);
            }
        }
        __syncthreads();

        float* Cs = (float*)smem;   // [BM][LDC] = 69632 B <= GEMM_SMEM
        #pragma unroll
        for (int i = 0; i < 2; i++)
            #pragma unroll
            for (int j = 0; j < 4; j++)
                wmma::store_matrix_sync(Cs + (wm * 32 + i * 16) * LDC + wn * 64 + j * 16,
                                        acc[i][j], LDC, wmma::mem_row_major);
        __syncthreads();

        for (int idx = tid; idx < BM * (BN / 8); idx += GEMM_THREADS) {
            int row = idx >> 4, q = idx & 15;
            int m = m_base + row;
            if (m >= cnt) continue;
            int n = n_base + q * 8;
            if (n >= Vc) continue;
            __half* srow = g_scratch + (size_t)g_tok[c][m] * VMAX;
            const float* src = Cs + row * LDC + q * 8;
            float4 bv0 = *(const float4*)(bias + n);
            float4 bv1 = *(const float4*)(bias + n + 4);
            __half2 h[4] = { __floats2half2_rn(src[0] + bv0.x, src[1] + bv0.y),
                             __floats2half2_rn(src[2] + bv0.z, src[3] + bv0.w),
                             __floats2half2_rn(src[4] + bv1.x, src[5] + bv1.y),
                             __floats2half2_rn(src[6] + bv1.z, src[7] + bv1.w) };
            *(uint4*)(srow + n) = *(const uint4*)h;
        }
        __syncthreads();   // Cs / stage buffers / s_tix reused next iteration
    }
}

// ---------------------------------------------------------------------------
// Kernel 3: fused lse + full-row output, register-resident logits.
// ---------------------------------------------------------------------------
__global__ __launch_bounds__(OUT_THREADS, 2) void out_kernel(float* __restrict__ out) {
    __shared__ float red[16];
    __shared__ float sh_bcast;

    const int t = blockIdx.x;
    const int c = g_clu[t];
    const int l = c * 20000;
    const int V = (c == 2) ? 10000 : 20000;
    const int nf4 = V >> 2;                         // 5000 or 2500
    const __half* __restrict__ rowp = g_scratch + (size_t)t * VMAX;
    const int tid = threadIdx.x;

    float4 r[RMAX];
    float lmax = -3.4e38f;
    #pragma unroll
    for (int it = 0; it < RMAX; it++) {
        int j = tid + it * OUT_THREADS;
        if (j < nf4) {
            uint2 u = *(const uint2*)(rowp + j * 4);
            float2 f0 = __half22float2(*(const __half2*)&u.x);
            float2 f1 = __half22float2(*(const __half2*)&u.y);
            r[it] = make_float4(f0.x, f0.y, f1.x, f1.y);
            lmax = fmaxf(lmax, fmaxf(fmaxf(r[it].x, r[it].y), fmaxf(r[it].z, r[it].w)));
        }
    }
    #pragma unroll
    for (int o = 16; o; o >>= 1) lmax = fmaxf(lmax, __shfl_xor_sync(0xffffffffu, lmax, o));
    if ((tid & 31) == 0) red[tid >> 5] = lmax;
    __syncthreads();
    if (tid < 32) {
        float v = (tid < 16) ? red[tid] : -3.4e38f;
        #pragma unroll
        for (int o = 8; o; o >>= 1) v = fmaxf(v, __shfl_xor_sync(0xffffffffu, v, o));
        if (tid == 0) sh_bcast = fmaxf(v, 0.0f);    // implicit zeros join the max
    }
    __syncthreads();
    const float M = sh_bcast;

    float lsum = 0.f;
    #pragma unroll
    for (int it = 0; it < RMAX; it++) {
        int j = tid + it * OUT_THREADS;
        if (j < nf4)
            lsum += __expf(r[it].x - M) + __expf(r[it].y - M)
                  + __expf(r[it].z - M) + __expf(r[it].w - M);
    }
    #pragma unroll
    for (int o = 16; o; o >>= 1) lsum += __shfl_xor_sync(0xffffffffu, lsum, o);
    __syncthreads();
    if ((tid & 31) == 0) red[tid >> 5] = lsum;
    __syncthreads();
    if (tid < 32) {
        float v = (tid < 16) ? red[tid] : 0.f;
        #pragma unroll
        for (int o = 8; o; o >>= 1) v += __shfl_xor_sync(0xffffffffu, v, o);
        if (tid == 0)
            sh_bcast = M + logf(v + (float)(VTOT - V) * __expf(-M));   // implicit zeros
    }
    __syncthreads();
    const float lse = sh_bcast;
    const float neg = -lse;

    float4* o4 = (float4*)(out + (size_t)t * VTOT);
    const int l4 = l >> 2;
    #pragma unroll
    for (int it = 0; it < RMAX; it++) {
        int j = tid + it * OUT_THREADS;
        if (j < nf4)
            __stcs(&o4[l4 + j], make_float4(r[it].x - lse, r[it].y - lse,
                                            r[it].z - lse, r[it].w - lse));
    }
    const float4 nv = make_float4(neg, neg, neg, neg);
    for (int j = tid; j < l4; j += OUT_THREADS) __stcs(&o4[j], nv);
    for (int j = l4 + nf4 + tid; j < VTOT / 4; j += OUT_THREADS) __stcs(&o4[j], nv);
}

// ---------------------------------------------------------------------------
// Launch (single stream)
// ---------------------------------------------------------------------------
extern "C" void kernel_launch(void* const* d_in, const int* in_sizes, int n_in,
                              void* d_out, int out_size) {
    const float* x  = (const float*)d_in[0];
    const int*   tg = (const int*)d_in[1];
    const float* w0 = (const float*)d_in[2];
    const float* w1 = (const float*)d_in[3];
    const float* w2 = (const float*)d_in[4];
    const float* b0 = (const float*)d_in[5];
    const float* b1 = (const float*)d_in[6];
    const float* b2 = (const float*)d_in[7];
    float* out = (float*)d_out;

    cudaFuncSetAttribute(gemm_kernel, cudaFuncAttributeMaxDynamicSharedMemorySize, GEMM_SMEM);

    int prep_blocks = (int)((TOTN / 8 + 255) / 256);
    prep_kernel<<<prep_blocks, 256>>>(x, w0, w1, w2, tg);

    gemm_kernel<<<GEMM_BLOCKS, GEMM_THREADS, GEMM_SMEM>>>(b0, b1, b2);

    out_kernel<<<NTOK, OUT_THREADS>>>(out);
}

// round 13
// speedup vs baseline: 1.0514x; 1.0247x over previous
#include <cuda_runtime.h>
#include <cuda_fp16.h>
#include <mma.h>
#include <cstdint>
#include <cstddef>

using namespace nvcuda;

// ---------------------------------------------------------------------------
// Problem constants
// ---------------------------------------------------------------------------
constexpr int NTOK = 2048;          // B*S
constexpr int DDIM = 256;
constexpr int VTOT = 50000;
constexpr int VMAX = 20000;

// GEMM tiling (R8/R10 config): BM=128 BN=128 BK=64, 3-stage cp.async pipeline
constexpr int BM = 128, BN = 128, BK = 64;
constexpr int LDS = BK + 8;                         // 72 halves = 144 B row stride
constexpr int LDC = BN + 8;                         // epilogue fp32 stride
constexpr int A_BYTES = BM * LDS * 2;               // 18432
constexpr int B_BYTES = BN * LDS * 2;               // 18432
constexpr int STAGE_BYTES = A_BYTES + B_BYTES;      // 36864
constexpr int PIPE = 3;
constexpr int GEMM_SMEM = PIPE * STAGE_BYTES;       // 110592
constexpr int GEMM_THREADS = 256;
constexpr int NCHUNK = DDIM / BK;                   // 4

constexpr int OUT_THREADS = 512;
constexpr int RMAX = 10;                            // ceil((20000/4)/512)

// element counts for the fp16 conversion
constexpr size_t XN  = (size_t)NTOK * DDIM;
constexpr size_t W0N = (size_t)20000 * DDIM;
constexpr size_t W1N = (size_t)20000 * DDIM;
constexpr size_t W2N = (size_t)10000 * DDIM;
constexpr size_t TOTN = XN + W0N + W1N + W2N;       // 13324288 (divisible by 8)

// ---------------------------------------------------------------------------
// Device scratch
// ---------------------------------------------------------------------------
__device__ int    g_cnt[3];
__device__ int    g_tok[3][NTOK];
__device__ int    g_clu[NTOK];
__device__ __half g_xh[XN];
__device__ __half g_wh[W0N + W1N + W2N];
__device__ __half g_scratch[(size_t)NTOK * VMAX];   // fp16 logits, stride VMAX

// ---------------------------------------------------------------------------
// Helpers
// ---------------------------------------------------------------------------
__device__ __forceinline__ void cp_async16(uint32_t dst, const void* src, bool pred) {
    int sz = pred ? 16 : 0;
    asm volatile("cp.async.cg.shared.global [%0], [%1], 16, %2;"
                 :: "r"(dst), "l"(src), "r"(sz));
}
__device__ __forceinline__ void cp_commit() { asm volatile("cp.async.commit_group;"); }
template <int N>
__device__ __forceinline__ void cp_wait() { asm volatile("cp.async.wait_group %0;" :: "n"(N)); }
__device__ __forceinline__ uint32_t smem_u32(const void* p) {
    uint32_t a;
    asm("{ .reg .u64 t; cvta.to.shared.u64 t, %1; cvt.u32.u64 %0, t; }" : "=r"(a) : "l"(p));
    return a;
}

// ---------------------------------------------------------------------------
// Kernel 1: fp32 -> fp16 conversion (8 elems/thread); block 0 builds lists.
// ---------------------------------------------------------------------------
__global__ void prep_kernel(const float* __restrict__ x,
                            const float* __restrict__ w0, const float* __restrict__ w1,
                            const float* __restrict__ w2, const int* __restrict__ tg)
{
    size_t i = (size_t)blockIdx.x * blockDim.x + threadIdx.x;
    size_t j = i * 8;
    if (j < TOTN) {
        const float* src; __half* dst;
        if (j < XN) { src = x + j; dst = g_xh + j; }
        else {
            size_t k = j - XN;
            if (k < W0N)            { src = w0 + k;               dst = g_wh + k; }
            else if (k < W0N + W1N) { src = w1 + (k - W0N);       dst = g_wh + k; }
            else                    { src = w2 + (k - W0N - W1N); dst = g_wh + k; }
        }
        float4 v0 = *(const float4*)src;
        float4 v1 = *(const float4*)(src + 4);
        __half2 h[4] = { __floats2half2_rn(v0.x, v0.y), __floats2half2_rn(v0.z, v0.w),
                         __floats2half2_rn(v1.x, v1.y), __floats2half2_rn(v1.z, v1.w) };
        *(uint4*)dst = *(const uint4*)h;
    }

    if (blockIdx.x == 0) {
        __shared__ int s_cnt[3];
        __shared__ int s_is64;
        if (threadIdx.x == 0) s_is64 = 1;
        if (threadIdx.x < 3) s_cnt[threadIdx.x] = 0;
        __syncthreads();
        for (int q = threadIdx.x; q < NTOK / 2; q += blockDim.x)
            if (tg[2 * q + 1] != 0) s_is64 = 0;
        __syncthreads();
        int is64 = s_is64;
        for (int t = threadIdx.x; t < NTOK; t += blockDim.x) {
            int v = is64 ? tg[2 * t] : tg[t];
            int c = (v < 20000) ? 0 : ((v < 40000) ? 1 : 2);
            g_clu[t] = c;
            int pos = atomicAdd(&s_cnt[c], 1);
            g_tok[c][pos] = t;
        }
        __syncthreads();
        if (threadIdx.x < 3) g_cnt[threadIdx.x] = s_cnt[threadIdx.x];
    }
}

// ---------------------------------------------------------------------------
// Kernel 2: grouped fp16 GEMM, BM=128/BN=128/BK=64, 3-stage cp.async pipeline
// (R10 configuration: oversubscribed HW-scheduled grid, dead blocks exit)
// ---------------------------------------------------------------------------
__global__ __launch_bounds__(GEMM_THREADS, 2) void gemm_kernel(
    const float* __restrict__ b0, const float* __restrict__ b1, const float* __restrict__ b2)
{
    extern __shared__ char smem[];
    const int c = blockIdx.z;
    const int cnt = g_cnt[c];
    const int m_base = blockIdx.x * BM;
    if (m_base >= cnt) return;
    const int Vc = (c == 2) ? 10000 : 20000;
    const int n_base = blockIdx.y * BN;
    if (n_base >= Vc) return;

    const size_t woff = (c == 0) ? 0 : ((c == 1) ? W0N : (W0N + W1N));
    const float* __restrict__ bias = (c == 0) ? b0 : ((c == 1) ? b1 : b2);

    const uint32_t sb = smem_u32(smem);
    const int tid  = threadIdx.x;
    const int warp = tid >> 5;
    const int wm = warp >> 1;       // 0..3 : 32-row slab
    const int wn = warp & 1;        // 0..1 : 64-col slab

    const __half* arow[4];
    #pragma unroll
    for (int j = 0; j < 4; j++) {
        int row = (tid + GEMM_THREADS * j) >> 3;
        int m = m_base + row;
        arow[j] = (m < cnt) ? (g_xh + (size_t)g_tok[c][m] * DDIM) : nullptr;
    }
    const __half* brow[4];
    bool bval[4];
    #pragma unroll
    for (int j = 0; j < 4; j++) {
        int row = (tid + GEMM_THREADS * j) >> 3;
        int n = n_base + row;
        bval[j] = (n < Vc);
        brow[j] = g_wh + (woff + (size_t)(bval[j] ? n : 0) * DDIM);
    }

    auto stage_load = [&](int s) {
        const uint32_t abase = sb + (s % PIPE) * STAGE_BYTES;
        const uint32_t bbase = abase + A_BYTES;
        #pragma unroll
        for (int j = 0; j < 4; j++) {
            int idx = tid + GEMM_THREADS * j;
            int row = idx >> 3, seg = idx & 7;
            const __half* src = arow[j] ? (arow[j] + s * BK + seg * 8) : g_xh;
            cp_async16(abase + row * (LDS * 2) + seg * 16, src, arow[j] != nullptr);
        }
        #pragma unroll
        for (int j = 0; j < 4; j++) {
            int idx = tid + GEMM_THREADS * j;
            int row = idx >> 3, seg = idx & 7;
            cp_async16(bbase + row * (LDS * 2) + seg * 16, brow[j] + s * BK + seg * 8, bval[j]);
        }
        cp_commit();
    };

    wmma::fragment<wmma::accumulator, 16, 16, 16, float> acc[2][4];
    #pragma unroll
    for (int i = 0; i < 2; i++)
        #pragma unroll
        for (int j = 0; j < 4; j++)
            wmma::fill_fragment(acc[i][j], 0.0f);

    stage_load(0); stage_load(1);

    #pragma unroll
    for (int k = 0; k < NCHUNK; k++) {
        if (k < NCHUNK - 1) cp_wait<1>(); else cp_wait<0>();
        __syncthreads();
        if (k + 2 < NCHUNK) stage_load(k + 2);
        const __half* As = (const __half*)(smem + (k % PIPE) * STAGE_BYTES);
        const __half* Bs = As + A_BYTES / 2;
        #pragma unroll
        for (int kk = 0; kk < BK; kk += 16) {
            wmma::fragment<wmma::matrix_a, 16, 16, 16, __half, wmma::row_major> af[2];
            wmma::fragment<wmma::matrix_b, 16, 16, 16, __half, wmma::col_major> bf[4];
            #pragma unroll
            for (int i = 0; i < 2; i++)
                wmma::load_matrix_sync(af[i], As + (wm * 32 + i * 16) * LDS + kk, LDS);
            #pragma unroll
            for (int j = 0; j < 4; j++)
                wmma::load_matrix_sync(bf[j], Bs + (wn * 64 + j * 16) * LDS + kk, LDS);
            #pragma unroll
            for (int i = 0; i < 2; i++)
                #pragma unroll
                for (int j = 0; j < 4; j++)
                    wmma::mma_sync(acc[i][j], af[i], bf[j], acc[i][j]);
        }
    }
    __syncthreads();

    float* Cs = (float*)smem;   // [BM][LDC] = 69632 B <= GEMM_SMEM
    #pragma unroll
    for (int i = 0; i < 2; i++)
        #pragma unroll
        for (int j = 0; j < 4; j++)
            wmma::store_matrix_sync(Cs + (wm * 32 + i * 16) * LDC + wn * 64 + j * 16,
                                    acc[i][j], LDC, wmma::mem_row_major);
    __syncthreads();

    for (int idx = tid; idx < BM * (BN / 8); idx += GEMM_THREADS) {
        int row = idx >> 4, q = idx & 15;
        int m = m_base + row;
        if (m >= cnt) continue;
        int n = n_base + q * 8;
        if (n >= Vc) continue;
        __half* srow = g_scratch + (size_t)g_tok[c][m] * VMAX;
        const float* src = Cs + row * LDC + q * 8;
        float4 bv0 = *(const float4*)(bias + n);
        float4 bv1 = *(const float4*)(bias + n + 4);
        __half2 h[4] = { __floats2half2_rn(src[0] + bv0.x, src[1] + bv0.y),
                         __floats2half2_rn(src[2] + bv0.z, src[3] + bv0.w),
                         __floats2half2_rn(src[4] + bv1.x, src[5] + bv1.y),
                         __floats2half2_rn(src[6] + bv1.z, src[7] + bv1.w) };
        *(uint4*)(srow + n) = *(const uint4*)h;
    }
}

// ---------------------------------------------------------------------------
// Kernel 3: fused lse + full-row output, register-resident logits.
// Scratch is read exactly once -> evict-first loads (__ldcs) to preserve L2.
// ---------------------------------------------------------------------------
__global__ __launch_bounds__(OUT_THREADS, 2) void out_kernel(float* __restrict__ out) {
    __shared__ float red[16];
    __shared__ float sh_bcast;

    const int t = blockIdx.x;
    const int c = g_clu[t];
    const int l = c * 20000;
    const int V = (c == 2) ? 10000 : 20000;
    const int nf4 = V >> 2;                         // 5000 or 2500
    const __half* __restrict__ rowp = g_scratch + (size_t)t * VMAX;
    const int tid = threadIdx.x;

    float4 r[RMAX];
    float lmax = -3.4e38f;
    #pragma unroll
    for (int it = 0; it < RMAX; it++) {
        int j = tid + it * OUT_THREADS;
        if (j < nf4) {
            uint2 u = __ldcs((const uint2*)(rowp + j * 4));
            float2 f0 = __half22float2(*(const __half2*)&u.x);
            float2 f1 = __half22float2(*(const __half2*)&u.y);
            r[it] = make_float4(f0.x, f0.y, f1.x, f1.y);
            lmax = fmaxf(lmax, fmaxf(fmaxf(r[it].x, r[it].y), fmaxf(r[it].z, r[it].w)));
        }
    }
    #pragma unroll
    for (int o = 16; o; o >>= 1) lmax = fmaxf(lmax, __shfl_xor_sync(0xffffffffu, lmax, o));
    if ((tid & 31) == 0) red[tid >> 5] = lmax;
    __syncthreads();
    if (tid < 32) {
        float v = (tid < 16) ? red[tid] : -3.4e38f;
        #pragma unroll
        for (int o = 8; o; o >>= 1) v = fmaxf(v, __shfl_xor_sync(0xffffffffu, v, o));
        if (tid == 0) sh_bcast = fmaxf(v, 0.0f);    // implicit zeros join the max
    }
    __syncthreads();
    const float M = sh_bcast;

    float lsum = 0.f;
    #pragma unroll
    for (int it = 0; it < RMAX; it++) {
        int j = tid + it * OUT_THREADS;
        if (j < nf4)
            lsum += __expf(r[it].x - M) + __expf(r[it].y - M)
                  + __expf(r[it].z - M) + __expf(r[it].w - M);
    }
    #pragma unroll
    for (int o = 16; o; o >>= 1) lsum += __shfl_xor_sync(0xffffffffu, lsum, o);
    __syncthreads();
    if ((tid & 31) == 0) red[tid >> 5] = lsum;
    __syncthreads();
    if (tid < 32) {
        float v = (tid < 16) ? red[tid] : 0.f;
        #pragma unroll
        for (int o = 8; o; o >>= 1) v += __shfl_xor_sync(0xffffffffu, v, o);
        if (tid == 0)
            sh_bcast = M + logf(v + (float)(VTOT - V) * __expf(-M));   // implicit zeros
    }
    __syncthreads();
    const float lse = sh_bcast;
    const float neg = -lse;

    float4* o4 = (float4*)(out + (size_t)t * VTOT);
    const int l4 = l >> 2;
    #pragma unroll
    for (int it = 0; it < RMAX; it++) {
        int j = tid + it * OUT_THREADS;
        if (j < nf4)
            __stcs(&o4[l4 + j], make_float4(r[it].x - lse, r[it].y - lse,
                                            r[it].z - lse, r[it].w - lse));
    }
    const float4 nv = make_float4(neg, neg, neg, neg);
    for (int j = tid; j < l4; j += OUT_THREADS) __stcs(&o4[j], nv);
    for (int j = l4 + nf4 + tid; j < VTOT / 4; j += OUT_THREADS) __stcs(&o4[j], nv);
}

// ---------------------------------------------------------------------------
// Launch (single stream, R10 structure)
// ---------------------------------------------------------------------------
extern "C" void kernel_launch(void* const* d_in, const int* in_sizes, int n_in,
                              void* d_out, int out_size) {
    const float* x  = (const float*)d_in[0];
    const int*   tg = (const int*)d_in[1];
    const float* w0 = (const float*)d_in[2];
    const float* w1 = (const float*)d_in[3];
    const float* w2 = (const float*)d_in[4];
    const float* b0 = (const float*)d_in[5];
    const float* b1 = (const float*)d_in[6];
    const float* b2 = (const float*)d_in[7];
    float* out = (float*)d_out;

    cudaFuncSetAttribute(gemm_kernel, cudaFuncAttributeMaxDynamicSharedMemorySize, GEMM_SMEM);

    int prep_blocks = (int)((TOTN / 8 + 255) / 256);
    prep_kernel<<<prep_blocks, 256>>>(x, w0, w1, w2, tg);

    dim3 grid((NTOK + BM - 1) / BM, (VMAX + BN - 1) / BN, 3);   // (16, 157, 3)
    gemm_kernel<<<grid, GEMM_THREADS, GEMM_SMEM>>>(b0, b1, b2);

    out_kernel<<<NTOK, OUT_THREADS>>>(out);
}

// round 14
// speedup vs baseline: 1.0545x; 1.0029x over previous
#include <cuda_runtime.h>
#include <cuda_fp16.h>
#include <mma.h>
#include <cstdint>
#include <cstddef>

using namespace nvcuda;

// ---------------------------------------------------------------------------
// Problem constants
// ---------------------------------------------------------------------------
constexpr int NTOK = 2048;          // B*S
constexpr int DDIM = 256;
constexpr int VTOT = 50000;
constexpr int VMAX = 20000;

// GEMM tiling (R8/R10 config): BM=128 BN=128 BK=64, 3-stage cp.async pipeline
constexpr int BM = 128, BN = 128, BK = 64;
constexpr int LDS = BK + 8;                         // 72 halves = 144 B row stride
constexpr int LDC = BN + 8;                         // epilogue fp32 stride
constexpr int A_BYTES = BM * LDS * 2;               // 18432
constexpr int B_BYTES = BN * LDS * 2;               // 18432
constexpr int STAGE_BYTES = A_BYTES + B_BYTES;      // 36864
constexpr int PIPE = 3;
constexpr int GEMM_SMEM = PIPE * STAGE_BYTES;       // 110592
constexpr int GEMM_THREADS = 256;
constexpr int NCHUNK = DDIM / BK;                   // 4

// Flattened GEMM grid: y encodes (cluster, nb); x covers up to 1280 tok/cluster
constexpr int NB0 = (20000 + BN - 1) / BN;          // 157
constexpr int NB2 = (10000 + BN - 1) / BN;          // 79
constexpr int GRID_Y = NB0 + NB0 + NB2;             // 393
constexpr int GRID_X = 10;                          // 10*128 = 1280 tokens margin

constexpr int OUT_THREADS = 512;
constexpr int RMAX = 10;                            // ceil((20000/4)/512)

// element counts for the fp16 conversion
constexpr size_t XN  = (size_t)NTOK * DDIM;
constexpr size_t W0N = (size_t)20000 * DDIM;
constexpr size_t W1N = (size_t)20000 * DDIM;
constexpr size_t W2N = (size_t)10000 * DDIM;
constexpr size_t TOTN = XN + W0N + W1N + W2N;       // 13324288 (divisible by 8)

// ---------------------------------------------------------------------------
// Device scratch
// ---------------------------------------------------------------------------
__device__ int    g_cnt[3];
__device__ int    g_tok[3][NTOK];
__device__ int    g_clu[NTOK];
__device__ __half g_xh[XN];
__device__ __half g_wh[W0N + W1N + W2N];
__device__ __half g_scratch[(size_t)NTOK * VMAX];   // fp16 logits, stride VMAX

// ---------------------------------------------------------------------------
// Helpers
// ---------------------------------------------------------------------------
__device__ __forceinline__ void cp_async16(uint32_t dst, const void* src, bool pred) {
    int sz = pred ? 16 : 0;
    asm volatile("cp.async.cg.shared.global [%0], [%1], 16, %2;"
                 :: "r"(dst), "l"(src), "r"(sz));
}
__device__ __forceinline__ void cp_commit() { asm volatile("cp.async.commit_group;"); }
template <int N>
__device__ __forceinline__ void cp_wait() { asm volatile("cp.async.wait_group %0;" :: "n"(N)); }
__device__ __forceinline__ uint32_t smem_u32(const void* p) {
    uint32_t a;
    asm("{ .reg .u64 t; cvta.to.shared.u64 t, %1; cvt.u32.u64 %0, t; }" : "=r"(a) : "l"(p));
    return a;
}

// ---------------------------------------------------------------------------
// Kernel 1: fp32 -> fp16 conversion (8 elems/thread); block 0 builds lists.
// ---------------------------------------------------------------------------
__global__ void prep_kernel(const float* __restrict__ x,
                            const float* __restrict__ w0, const float* __restrict__ w1,
                            const float* __restrict__ w2, const int* __restrict__ tg)
{
    size_t i = (size_t)blockIdx.x * blockDim.x + threadIdx.x;
    size_t j = i * 8;
    if (j < TOTN) {
        const float* src; __half* dst;
        if (j < XN) { src = x + j; dst = g_xh + j; }
        else {
            size_t k = j - XN;
            if (k < W0N)            { src = w0 + k;               dst = g_wh + k; }
            else if (k < W0N + W1N) { src = w1 + (k - W0N);       dst = g_wh + k; }
            else                    { src = w2 + (k - W0N - W1N); dst = g_wh + k; }
        }
        float4 v0 = *(const float4*)src;
        float4 v1 = *(const float4*)(src + 4);
        __half2 h[4] = { __floats2half2_rn(v0.x, v0.y), __floats2half2_rn(v0.z, v0.w),
                         __floats2half2_rn(v1.x, v1.y), __floats2half2_rn(v1.z, v1.w) };
        *(uint4*)dst = *(const uint4*)h;
    }

    if (blockIdx.x == 0) {
        __shared__ int s_cnt[3];
        __shared__ int s_is64;
        if (threadIdx.x == 0) s_is64 = 1;
        if (threadIdx.x < 3) s_cnt[threadIdx.x] = 0;
        __syncthreads();
        for (int q = threadIdx.x; q < NTOK / 2; q += blockDim.x)
            if (tg[2 * q + 1] != 0) s_is64 = 0;
        __syncthreads();
        int is64 = s_is64;
        for (int t = threadIdx.x; t < NTOK; t += blockDim.x) {
            int v = is64 ? tg[2 * t] : tg[t];
            int c = (v < 20000) ? 0 : ((v < 40000) ? 1 : 2);
            g_clu[t] = c;
            int pos = atomicAdd(&s_cnt[c], 1);
            g_tok[c][pos] = t;
        }
        __syncthreads();
        if (threadIdx.x < 3) g_cnt[threadIdx.x] = s_cnt[threadIdx.x];
    }
}

// ---------------------------------------------------------------------------
// Kernel 2: grouped fp16 GEMM, flattened (cluster, nb) grid, HW-scheduled
// ---------------------------------------------------------------------------
__global__ __launch_bounds__(GEMM_THREADS, 2) void gemm_kernel(
    const float* __restrict__ b0, const float* __restrict__ b1, const float* __restrict__ b2)
{
    extern __shared__ char smem[];
    // Decode y -> (cluster, nb)
    const int y = blockIdx.y;
    const int c  = (y < NB0) ? 0 : ((y < 2 * NB0) ? 1 : 2);
    const int nb = (y < NB0) ? y : ((y < 2 * NB0) ? (y - NB0) : (y - 2 * NB0));

    const int cnt = g_cnt[c];
    const int m_base = blockIdx.x * BM;
    if (m_base >= cnt) return;
    const int Vc = (c == 2) ? 10000 : 20000;
    const int n_base = nb * BN;

    const size_t woff = (c == 0) ? 0 : ((c == 1) ? W0N : (W0N + W1N));
    const float* __restrict__ bias = (c == 0) ? b0 : ((c == 1) ? b1 : b2);

    const uint32_t sb = smem_u32(smem);
    const int tid  = threadIdx.x;
    const int warp = tid >> 5;
    const int wm = warp >> 1;       // 0..3 : 32-row slab
    const int wn = warp & 1;        // 0..1 : 64-col slab

    const __half* arow[4];
    #pragma unroll
    for (int j = 0; j < 4; j++) {
        int row = (tid + GEMM_THREADS * j) >> 3;
        int m = m_base + row;
        arow[j] = (m < cnt) ? (g_xh + (size_t)g_tok[c][m] * DDIM) : nullptr;
    }
    const __half* brow[4];
    bool bval[4];
    #pragma unroll
    for (int j = 0; j < 4; j++) {
        int row = (tid + GEMM_THREADS * j) >> 3;
        int n = n_base + row;
        bval[j] = (n < Vc);
        brow[j] = g_wh + (woff + (size_t)(bval[j] ? n : 0) * DDIM);
    }

    auto stage_load = [&](int s) {
        const uint32_t abase = sb + (s % PIPE) * STAGE_BYTES;
        const uint32_t bbase = abase + A_BYTES;
        #pragma unroll
        for (int j = 0; j < 4; j++) {
            int idx = tid + GEMM_THREADS * j;
            int row = idx >> 3, seg = idx & 7;
            const __half* src = arow[j] ? (arow[j] + s * BK + seg * 8) : g_xh;
            cp_async16(abase + row * (LDS * 2) + seg * 16, src, arow[j] != nullptr);
        }
        #pragma unroll
        for (int j = 0; j < 4; j++) {
            int idx = tid + GEMM_THREADS * j;
            int row = idx >> 3, seg = idx & 7;
            cp_async16(bbase + row * (LDS * 2) + seg * 16, brow[j] + s * BK + seg * 8, bval[j]);
        }
        cp_commit();
    };

    wmma::fragment<wmma::accumulator, 16, 16, 16, float> acc[2][4];
    #pragma unroll
    for (int i = 0; i < 2; i++)
        #pragma unroll
        for (int j = 0; j < 4; j++)
            wmma::fill_fragment(acc[i][j], 0.0f);

    stage_load(0); stage_load(1);

    #pragma unroll
    for (int k = 0; k < NCHUNK; k++) {
        if (k < NCHUNK - 1) cp_wait<1>(); else cp_wait<0>();
        __syncthreads();
        if (k + 2 < NCHUNK) stage_load(k + 2);
        const __half* As = (const __half*)(smem + (k % PIPE) * STAGE_BYTES);
        const __half* Bs = As + A_BYTES / 2;
        #pragma unroll
        for (int kk = 0; kk < BK; kk += 16) {
            wmma::fragment<wmma::matrix_a, 16, 16, 16, __half, wmma::row_major> af[2];
            wmma::fragment<wmma::matrix_b, 16, 16, 16, __half, wmma::col_major> bf[4];
            #pragma unroll
            for (int i = 0; i < 2; i++)
                wmma::load_matrix_sync(af[i], As + (wm * 32 + i * 16) * LDS + kk, LDS);
            #pragma unroll
            for (int j = 0; j < 4; j++)
                wmma::load_matrix_sync(bf[j], Bs + (wn * 64 + j * 16) * LDS + kk, LDS);
            #pragma unroll
            for (int i = 0; i < 2; i++)
                #pragma unroll
                for (int j = 0; j < 4; j++)
                    wmma::mma_sync(acc[i][j], af[i], bf[j], acc[i][j]);
        }
    }
    __syncthreads();

    float* Cs = (float*)smem;   // [BM][LDC] = 69632 B <= GEMM_SMEM
    #pragma unroll
    for (int i = 0; i < 2; i++)
        #pragma unroll
        for (int j = 0; j < 4; j++)
            wmma::store_matrix_sync(Cs + (wm * 32 + i * 16) * LDC + wn * 64 + j * 16,
                                    acc[i][j], LDC, wmma::mem_row_major);
    __syncthreads();

    for (int idx = tid; idx < BM * (BN / 8); idx += GEMM_THREADS) {
        int row = idx >> 4, q = idx & 15;
        int m = m_base + row;
        if (m >= cnt) continue;
        int n = n_base + q * 8;
        if (n >= Vc) continue;
        __half* srow = g_scratch + (size_t)g_tok[c][m] * VMAX;
        const float* src = Cs + row * LDC + q * 8;
        float4 bv0 = *(const float4*)(bias + n);
        float4 bv1 = *(const float4*)(bias + n + 4);
        __half2 h[4] = { __floats2half2_rn(src[0] + bv0.x, src[1] + bv0.y),
                         __floats2half2_rn(src[2] + bv0.z, src[3] + bv0.w),
                         __floats2half2_rn(src[4] + bv1.x, src[5] + bv1.y),
                         __floats2half2_rn(src[6] + bv1.z, src[7] + bv1.w) };
        *(uint4*)(srow + n) = *(const uint4*)h;
    }
}

// ---------------------------------------------------------------------------
// Kernel 3: fused lse + full-row output, register-resident logits.
// Scratch is read exactly once -> evict-first loads (__ldcs) to preserve L2.
// ---------------------------------------------------------------------------
__global__ __launch_bounds__(OUT_THREADS, 2) void out_kernel(float* __restrict__ out) {
    __shared__ float red[16];
    __shared__ float sh_bcast;

    const int t = blockIdx.x;
    const int c = g_clu[t];
    const int l = c * 20000;
    const int V = (c == 2) ? 10000 : 20000;
    const int nf4 = V >> 2;                         // 5000 or 2500
    const __half* __restrict__ rowp = g_scratch + (size_t)t * VMAX;
    const int tid = threadIdx.x;

    float4 r[RMAX];
    float lmax = -3.4e38f;
    #pragma unroll
    for (int it = 0; it < RMAX; it++) {
        int j = tid + it * OUT_THREADS;
        if (j < nf4) {
            uint2 u = __ldcs((const uint2*)(rowp + j * 4));
            float2 f0 = __half22float2(*(const __half2*)&u.x);
            float2 f1 = __half22float2(*(const __half2*)&u.y);
            r[it] = make_float4(f0.x, f0.y, f1.x, f1.y);
            lmax = fmaxf(lmax, fmaxf(fmaxf(r[it].x, r[it].y), fmaxf(r[it].z, r[it].w)));
        }
    }
    #pragma unroll
    for (int o = 16; o; o >>= 1) lmax = fmaxf(lmax, __shfl_xor_sync(0xffffffffu, lmax, o));
    if ((tid & 31) == 0) red[tid >> 5] = lmax;
    __syncthreads();
    if (tid < 32) {
        float v = (tid < 16) ? red[tid] : -3.4e38f;
        #pragma unroll
        for (int o = 8; o; o >>= 1) v = fmaxf(v, __shfl_xor_sync(0xffffffffu, v, o));
        if (tid == 0) sh_bcast = fmaxf(v, 0.0f);    // implicit zeros join the max
    }
    __syncthreads();
    const float M = sh_bcast;

    float lsum = 0.f;
    #pragma unroll
    for (int it = 0; it < RMAX; it++) {
        int j = tid + it * OUT_THREADS;
        if (j < nf4)
            lsum += __expf(r[it].x - M) + __expf(r[it].y - M)
                  + __expf(r[it].z - M) + __expf(r[it].w - M);
    }
    #pragma unroll
    for (int o = 16; o; o >>= 1) lsum += __shfl_xor_sync(0xffffffffu, lsum, o);
    __syncthreads();
    if ((tid & 31) == 0) red[tid >> 5] = lsum;
    __syncthreads();
    if (tid < 32) {
        float v = (tid < 16) ? red[tid] : 0.f;
        #pragma unroll
        for (int o = 8; o; o >>= 1) v += __shfl_xor_sync(0xffffffffu, v, o);
        if (tid == 0)
            sh_bcast = M + logf(v + (float)(VTOT - V) * __expf(-M));   // implicit zeros
    }
    __syncthreads();
    const float lse = sh_bcast;
    const float neg = -lse;

    float4* o4 = (float4*)(out + (size_t)t * VTOT);
    const int l4 = l >> 2;
    #pragma unroll
    for (int it = 0; it < RMAX; it++) {
        int j = tid + it * OUT_THREADS;
        if (j < nf4)
            __stcs(&o4[l4 + j], make_float4(r[it].x - lse, r[it].y - lse,
                                            r[it].z - lse, r[it].w - lse));
    }
    const float4 nv = make_float4(neg, neg, neg, neg);
    for (int j = tid; j < l4; j += OUT_THREADS) __stcs(&o4[j], nv);
    for (int j = l4 + nf4 + tid; j < VTOT / 4; j += OUT_THREADS) __stcs(&o4[j], nv);
}

// ---------------------------------------------------------------------------
// Launch (single stream)
// ---------------------------------------------------------------------------
extern "C" void kernel_launch(void* const* d_in, const int* in_sizes, int n_in,
                              void* d_out, int out_size) {
    const float* x  = (const float*)d_in[0];
    const int*   tg = (const int*)d_in[1];
    const float* w0 = (const float*)d_in[2];
    const float* w1 = (const float*)d_in[3];
    const float* w2 = (const float*)d_in[4];
    const float* b0 = (const float*)d_in[5];
    const float* b1 = (const float*)d_in[6];
    const float* b2 = (const float*)d_in[7];
    float* out = (float*)d_out;

    cudaFuncSetAttribute(gemm_kernel, cudaFuncAttributeMaxDynamicSharedMemorySize, GEMM_SMEM);

    int prep_blocks = (int)((TOTN / 8 + 255) / 256);
    prep_kernel<<<prep_blocks, 256>>>(x, w0, w1, w2, tg);

    dim3 grid(GRID_X, GRID_Y);                      // (10, 393) flattened
    gemm_kernel<<<grid, GEMM_THREADS, GEMM_SMEM>>>(b0, b1, b2);

    out_kernel<<<NTOK, OUT_THREADS>>>(out);
}